// round 12
// baseline (speedup 1.0000x reference)
#include <cuda_runtime.h>

#define BB 256
#define TT 2048
#define II 128
#define HH 256
#define AA 8

typedef unsigned long long ull;

// 512MB scratch for xproj[b][t][h]
__device__ float g_xproj[(size_t)BB * TT * HH];

__device__ __forceinline__ ull ffma2(ull a, ull b, ull c) {
  ull d;
  asm("fma.rn.f32x2 %0, %1, %2, %3;" : "=l"(d) : "l"(a), "l"(b), "l"(c));
  return d;
}
__device__ __forceinline__ ull add2(ull a, ull b) {
  ull d;
  asm("add.rn.f32x2 %0, %1, %2;" : "=l"(d) : "l"(a), "l"(b));
  return d;
}
__device__ __forceinline__ ull pack2(float lo, float hi) {
  ull d;
  asm("mov.b64 %0, {%1, %2};" : "=l"(d) : "f"(lo), "f"(hi));
  return d;
}
__device__ __forceinline__ float hsum2(ull v) {
  float lo, hi;
  asm("mov.b64 {%0, %1}, %2;" : "=f"(lo), "=f"(hi) : "l"(v));
  return lo + hi;
}
__device__ __forceinline__ void unpack2(ull v, float& lo, float& hi) {
  asm("mov.b64 {%0, %1}, %2;" : "=f"(lo), "=f"(hi) : "l"(v));
}

// ---------------------------------------------------------------------------
// Kernel 1: xproj[r][j] = sum_k x[r][k] * W_ih[j][k]
// 512 threads: thread = (jp = tid>>2 -> j in {2jp, 2jp+1}, kq = tid&3 ->
// 32-k window). W in 32 ull regs; each broadcast LDS.128 of x feeds 4 FFMA2
// (fma-bound, LDS at 50%). 8-row double-buffered chunks, ONE barrier per
// chunk (R6's proven quantum). In-warp quad reduce-scatter over lane bits
// 0-1 (kq): lane ends owning rows {kq, kq+4} as packed (j0,j1) float2.
// ---------------------------------------------------------------------------
__global__ void __launch_bounds__(512) xproj_kernel(
    const float* __restrict__ x, const float* __restrict__ W_ih) {
  __shared__ float sX[2][1024];  // 8 rows x 128 floats, double buffered

  const int tid = threadIdx.x;
  const int kq = tid & 3;
  const int jp = tid >> 2;       // 0..127
  const int j0 = 2 * jp;

  // W regs: 2 j x 32 k = 32 ull
  ull w0[16], w1[16];
  {
    const float4* wp0 =
        reinterpret_cast<const float4*>(W_ih + j0 * II + kq * 32);
    const float4* wp1 =
        reinterpret_cast<const float4*>(W_ih + (j0 + 1) * II + kq * 32);
    #pragma unroll
    for (int q = 0; q < 8; ++q) {
      float4 f0 = __ldg(wp0 + q);
      float4 f1 = __ldg(wp1 + q);
      w0[2 * q]     = pack2(f0.x, f0.y);
      w0[2 * q + 1] = pack2(f0.z, f0.w);
      w1[2 * q]     = pack2(f1.x, f1.y);
      w1[2 * q + 1] = pack2(f1.z, f1.w);
    }
  }

  const size_t rowbase = (size_t)blockIdx.x * 256;
  const float4* xg4 = reinterpret_cast<const float4*>(x + rowbase * II);

  if (tid < 256) {
    reinterpret_cast<float4*>(sX[0])[tid] = __ldg(xg4 + tid);
  }
  __syncthreads();

  for (int c = 0; c < 32; ++c) {
    float4 pf;
    if (c < 31 && tid < 256) pf = __ldg(xg4 + (c + 1) * 256 + tid);

    const float* cur = sX[c & 1];
    ull a0[8], a1[8];
    #pragma unroll
    for (int r = 0; r < 8; ++r) { a0[r] = 0ull; a1[r] = 0ull; }

    #pragma unroll
    for (int r = 0; r < 8; ++r) {
      const ulonglong2* xr =
          reinterpret_cast<const ulonglong2*>(cur + r * II + kq * 32);
      #pragma unroll
      for (int q = 0; q < 8; ++q) {
        ulonglong2 xv = xr[q];
        a0[r] = ffma2(w0[2 * q],     xv.x, a0[r]);
        a1[r] = ffma2(w1[2 * q],     xv.x, a1[r]);
        a0[r] = ffma2(w0[2 * q + 1], xv.y, a0[r]);
        a1[r] = ffma2(w1[2 * q + 1], xv.y, a1[r]);
      }
    }

    if (c < 31 && tid < 256) {
      reinterpret_cast<float4*>(sX[(c + 1) & 1])[tid] = pf;
    }

    // per-row packed (j0, j1) partial
    ull itm[8];
    #pragma unroll
    for (int r = 0; r < 8; ++r) {
      itm[r] = pack2(hsum2(a0[r]), hsum2(a1[r]));
    }

    // quad reduce-scatter over lane bits 0-1 (kq)
    const bool b0 = (tid & 1), b1 = (tid & 2);
    ull k4[4];
    #pragma unroll
    for (int i = 0; i < 4; ++i) {
      ull keep = b0 ? itm[2 * i + 1] : itm[2 * i];
      ull give = b0 ? itm[2 * i]     : itm[2 * i + 1];
      k4[i] = add2(keep, __shfl_xor_sync(0xffffffffu, give, 1));
    }
    ull f2[2];
    #pragma unroll
    for (int m = 0; m < 2; ++m) {
      ull keep = b1 ? k4[2 * m + 1] : k4[2 * m];
      ull give = b1 ? k4[2 * m]     : k4[2 * m + 1];
      f2[m] = add2(keep, __shfl_xor_sync(0xffffffffu, give, 2));
    }
    // f2[m] = full sum for row (c*8 + kq + 4m), columns (j0, j1)
    #pragma unroll
    for (int m = 0; m < 2; ++m) {
      float r0, r1;
      unpack2(f2[m], r0, r1);
      float* op = g_xproj + (rowbase + (size_t)c * 8 + kq + 4 * m) * HH + j0;
      *reinterpret_cast<float2*>(op) = make_float2(r0, r1);
    }

    __syncthreads();
  }
}

// ---------------------------------------------------------------------------
// Kernel 2: recurrence — VERBATIM R6 (proven 2.47 ms). 128 CTAs x 512 thr,
// one CTA per batch pair. Thread (JQ = tid>>3, KH = tid&7): j in [4JQ,4JQ+4),
// k in [32KH, 32KH+32). W: 80 floats/j-group in regs + 48 via conflict-free
// LDS.128. h double-buffered; in-warp octet reduce via shfl_xor(1,2,4);
// one barrier per step.
// ---------------------------------------------------------------------------
__global__ void __launch_bounds__(512, 1) recurrence_kernel(
    const float* __restrict__ hx, const float* __restrict__ W_hh,
    const float* __restrict__ W_actor, const float* __restrict__ W_critic,
    float* __restrict__ out) {
  extern __shared__ float smem[];
  ulonglong2* sW = reinterpret_cast<ulonglong2*>(smem);   // 12*512 u2
  float* shb = smem + 12 * 512 * 4;                       // [2 parity][2 b][288]

  const int tid = threadIdx.x;
  const int JQ = tid >> 3;       // 0..63
  const int KH = tid & 7;        // 0..7
  const int jb = JQ * 4;
  const int kb = KH * 32;
  const int b0g = blockIdx.x * 2;

  const int jf = JQ * 4 + (KH & 3);
  const int bf = KH >> 2;

  // ---- stage W regs: q = 0..4 ----
  ull wr[4][10];
  #pragma unroll
  for (int j = 0; j < 4; ++j) {
    const float4* wp =
        reinterpret_cast<const float4*>(W_hh + (jb + j) * HH + kb);
    #pragma unroll
    for (int q = 0; q < 5; ++q) {
      float4 f = __ldg(wp + q);
      wr[j][2 * q]     = pack2(f.x, f.y);
      wr[j][2 * q + 1] = pack2(f.z, f.w);
    }
  }
  // ---- stage W smem: q = 5..7 ----
  #pragma unroll
  for (int q = 5; q < 8; ++q) {
    #pragma unroll
    for (int j = 0; j < 4; ++j) {
      float4 f = __ldg(reinterpret_cast<const float4*>(
          W_hh + (jb + j) * HH + kb) + q);
      ulonglong2 v;
      v.x = pack2(f.x, f.y);
      v.y = pack2(f.z, f.w);
      sW[((q - 5) * 4 + j) * 512 + tid] = v;
    }
  }

  // ---- init h ----
  float h_old = hx[(b0g + bf) * HH + jf];
  shb[bf * 288 + (jf >> 5) * 36 + (jf & 31)] = h_old;
  __syncthreads();

  const float* xqp = g_xproj + ((size_t)(b0g + bf) * TT) * HH + jf;
  float xq_cur = __ldg(xqp);

  for (int t = 0; t < TT; ++t) {
    const int rp = t & 1;
    float xq_nxt = 0.0f;
    if (t + 1 < TT) xq_nxt = __ldg(xqp + (size_t)(t + 1) * HH);

    const float* hbase = shb + rp * 576;
    const ulonglong2* hp0 =
        reinterpret_cast<const ulonglong2*>(hbase + KH * 36);
    const ulonglong2* hp1 =
        reinterpret_cast<const ulonglong2*>(hbase + 288 + KH * 36);

    ull a[8];
    #pragma unroll
    for (int i = 0; i < 8; ++i) a[i] = 0ull;

    #pragma unroll
    for (int q = 0; q < 8; ++q) {
      ulonglong2 v0 = hp0[q];
      ulonglong2 v1 = hp1[q];
      if (q < 5) {
        #pragma unroll
        for (int j = 0; j < 4; ++j) {
          a[j]     = ffma2(wr[j][2 * q],     v0.x, a[j]);
          a[j]     = ffma2(wr[j][2 * q + 1], v0.y, a[j]);
          a[4 + j] = ffma2(wr[j][2 * q],     v1.x, a[4 + j]);
          a[4 + j] = ffma2(wr[j][2 * q + 1], v1.y, a[4 + j]);
        }
      } else {
        #pragma unroll
        for (int j = 0; j < 4; ++j) {
          ulonglong2 wv = sW[((q - 5) * 4 + j) * 512 + tid];
          a[j]     = ffma2(wv.x, v0.x, a[j]);
          a[j]     = ffma2(wv.y, v0.y, a[j]);
          a[4 + j] = ffma2(wv.x, v1.x, a[4 + j]);
          a[4 + j] = ffma2(wv.y, v1.y, a[4 + j]);
        }
      }
    }

    // ---- octet reduce-scatter over KH bits ----
    const bool s0 = (tid & 1), s1 = (tid & 2), s2 = (tid & 4);
    ull w4[4];
    #pragma unroll
    for (int r = 0; r < 4; ++r) {
      ull keep = s0 ? a[2 * r + 1] : a[2 * r];
      ull give = s0 ? a[2 * r]     : a[2 * r + 1];
      ull recv = __shfl_xor_sync(0xffffffffu, give, 1);
      w4[r] = add2(keep, recv);
    }
    ull w2[2];
    #pragma unroll
    for (int r = 0; r < 2; ++r) {
      ull keep = s1 ? w4[2 * r + 1] : w4[2 * r];
      ull give = s1 ? w4[2 * r]     : w4[2 * r + 1];
      ull recv = __shfl_xor_sync(0xffffffffu, give, 2);
      w2[r] = add2(keep, recv);
    }
    ull keep = s2 ? w2[1] : w2[0];
    ull give = s2 ? w2[0] : w2[1];
    ull recv = __shfl_xor_sync(0xffffffffu, give, 4);
    ull tot = add2(keep, recv);

    // ---- finalize owned (b, j) ----
    float p = hsum2(tot) + xq_cur;
    h_old = 0.8f * h_old + 0.2f * fmaxf(p, 0.0f);
    shb[(rp ^ 1) * 576 + bf * 288 + (jf >> 5) * 36 + (jf & 31)] = h_old;
    xq_cur = xq_nxt;
    __syncthreads();
  }

  // -------- epilogue (final h in parity-0 buffer) --------
  const float* hf0 = shb;
  const float* hf1 = shb + 288;
  float* out_actor  = out;                 // [B][A]
  float* out_critic = out + BB * AA;       // [B]
  float* out_hx     = out + BB * AA + BB;  // [B][H]

  if (tid < HH) {
    int pj = (tid >> 5) * 36 + (tid & 31);
    out_hx[b0g * HH + tid]       = hf0[pj];
    out_hx[(b0g + 1) * HH + tid] = hf1[pj];
  }

  const int wid = tid >> 5, lane = tid & 31;
  if (wid < AA) {
    float pa0 = 0.f, pa1 = 0.f;
    for (int jj = lane; jj < HH; jj += 32) {
      int pj = (jj >> 5) * 36 + (jj & 31);
      float wa = W_actor[wid * HH + jj];
      pa0 += wa * hf0[pj];
      pa1 += wa * hf1[pj];
    }
    #pragma unroll
    for (int off = 16; off; off >>= 1) {
      pa0 += __shfl_down_sync(0xffffffffu, pa0, off);
      pa1 += __shfl_down_sync(0xffffffffu, pa1, off);
    }
    if (lane == 0) {
      out_actor[b0g * AA + wid]       = pa0;
      out_actor[(b0g + 1) * AA + wid] = pa1;
    }
  }
  if (wid == 8) {
    float pc0 = 0.f, pc1 = 0.f;
    for (int jj = lane; jj < HH; jj += 32) {
      int pj = (jj >> 5) * 36 + (jj & 31);
      float wc = W_critic[jj];
      pc0 += wc * hf0[pj];
      pc1 += wc * hf1[pj];
    }
    #pragma unroll
    for (int off = 16; off; off >>= 1) {
      pc0 += __shfl_down_sync(0xffffffffu, pc0, off);
      pc1 += __shfl_down_sync(0xffffffffu, pc1, off);
    }
    if (lane == 0) {
      out_critic[b0g]     = pc0;
      out_critic[b0g + 1] = pc1;
    }
  }
}

// ---------------------------------------------------------------------------
extern "C" void kernel_launch(void* const* d_in, const int* in_sizes, int n_in,
                              void* d_out, int out_size) {
  const float* x        = (const float*)d_in[0];
  const float* hx       = (const float*)d_in[1];
  const float* W_ih     = (const float*)d_in[2];
  const float* W_hh     = (const float*)d_in[3];
  const float* W_actor  = (const float*)d_in[4];
  const float* W_critic = (const float*)d_in[5];
  float* out = (float*)d_out;

  // recurrence smem: W 12*512*16B = 98304B + h 2*2*288*4B = 4608B
  const int smem2 = 98304 + 4608;
  cudaFuncSetAttribute(recurrence_kernel,
                       cudaFuncAttributeMaxDynamicSharedMemorySize, smem2);

  xproj_kernel<<<(BB * TT) / 256, 512>>>(x, W_ih);
  recurrence_kernel<<<BB / 2, 512, smem2>>>(hx, W_hh, W_actor, W_critic, out);
}

// round 13
// speedup vs baseline: 1.7277x; 1.7277x over previous
#include <cuda_runtime.h>

#define BB 256
#define TT 2048
#define II 128
#define HH 256
#define AA 8

typedef unsigned long long ull;

// 512MB scratch for xproj[b][t][h]
__device__ float g_xproj[(size_t)BB * TT * HH];

__device__ __forceinline__ ull ffma2(ull a, ull b, ull c) {
  ull d;
  asm("fma.rn.f32x2 %0, %1, %2, %3;" : "=l"(d) : "l"(a), "l"(b), "l"(c));
  return d;
}
__device__ __forceinline__ ull add2(ull a, ull b) {
  ull d;
  asm("add.rn.f32x2 %0, %1, %2;" : "=l"(d) : "l"(a), "l"(b));
  return d;
}
__device__ __forceinline__ ull pack2(float lo, float hi) {
  ull d;
  asm("mov.b64 %0, {%1, %2};" : "=l"(d) : "f"(lo), "f"(hi));
  return d;
}
__device__ __forceinline__ float hsum2(ull v) {
  float lo, hi;
  asm("mov.b64 {%0, %1}, %2;" : "=f"(lo), "=f"(hi) : "l"(v));
  return lo + hi;
}
__device__ __forceinline__ void unpack2(ull v, float& lo, float& hi) {
  asm("mov.b64 {%0, %1}, %2;" : "=f"(lo), "=f"(hi) : "l"(v));
}

// ---------------------------------------------------------------------------
// Kernel 1: xproj[r][j] = sum_k x[r][k] * W_ih[j][k]
// 512 threads: (jp = tid>>2 -> j in {2jp,2jp+1}, kq = tid&3 -> 32-k window,
// kq in lane bits 0-1). W in 32 ull regs. x staged in double-buffered 8-row
// chunks with a 16B XOR swizzle (chunk g of a row stored at g ^ (g>>3)) so
// the 4 kq windows hit distinct bank groups -> every LDS.128 is 1 wavefront.
// Each x load feeds 4 FFMA2 (2 j) -> fma-bound. Two 4-row passes keep live
// accumulators at 8 ull (no spill). In-quad shfl reduce-scatter; coalesced
// float2 stores. ONE barrier per chunk.
// ---------------------------------------------------------------------------
__global__ void __launch_bounds__(512) xproj_kernel(
    const float* __restrict__ x, const float* __restrict__ W_ih) {
  __shared__ float sX[2][1024];  // 8 rows x 128 floats, double buffered

  const int tid = threadIdx.x;
  const int kq = tid & 3;
  const int jp = tid >> 2;       // 0..127
  const int j0 = 2 * jp;

  // W regs: 2 j x 32 k = 32 ull
  ull w0[16], w1[16];
  {
    const float4* wp0 =
        reinterpret_cast<const float4*>(W_ih + j0 * II + kq * 32);
    const float4* wp1 =
        reinterpret_cast<const float4*>(W_ih + (j0 + 1) * II + kq * 32);
    #pragma unroll
    for (int q = 0; q < 8; ++q) {
      float4 f0 = __ldg(wp0 + q);
      float4 f1 = __ldg(wp1 + q);
      w0[2 * q]     = pack2(f0.x, f0.y);
      w0[2 * q + 1] = pack2(f0.z, f0.w);
      w1[2 * q]     = pack2(f1.x, f1.y);
      w1[2 * q + 1] = pack2(f1.z, f1.w);
    }
  }

  const size_t rowbase = (size_t)blockIdx.x * 256;
  const float4* xg4 = reinterpret_cast<const float4*>(x + rowbase * II);

  // stage chunk 0 (swizzled: 16B chunk g of row -> g ^ (g>>3))
  if (tid < 256) {
    float4 v = __ldg(xg4 + tid);
    int row = tid >> 5, gg = tid & 31;
    reinterpret_cast<float4*>(sX[0])[row * 32 + (gg ^ (gg >> 3))] = v;
  }
  __syncthreads();

  for (int c = 0; c < 32; ++c) {
    float4 pf;
    if (c < 31 && tid < 256) pf = __ldg(xg4 + (c + 1) * 256 + tid);

    const ulonglong2* cur =
        reinterpret_cast<const ulonglong2*>(sX[c & 1]);
    const bool b0 = (tid & 1), b1 = (tid & 2);

    #pragma unroll
    for (int p = 0; p < 2; ++p) {
      ull a0[4], a1[4];
      #pragma unroll
      for (int r = 0; r < 4; ++r) { a0[r] = 0ull; a1[r] = 0ull; }

      #pragma unroll
      for (int r = 0; r < 4; ++r) {
        const int rowi = 4 * p + r;
        #pragma unroll
        for (int q = 0; q < 8; ++q) {
          // logical chunk q of window kq lives at physical kq*8 + (q^kq)
          ulonglong2 xv = cur[rowi * 32 + kq * 8 + (q ^ kq)];
          a0[r] = ffma2(w0[2 * q],     xv.x, a0[r]);
          a1[r] = ffma2(w1[2 * q],     xv.x, a1[r]);
          a0[r] = ffma2(w0[2 * q + 1], xv.y, a0[r]);
          a1[r] = ffma2(w1[2 * q + 1], xv.y, a1[r]);
        }
      }

      // per-row packed (j0, j1) partials
      ull itm[4];
      #pragma unroll
      for (int r = 0; r < 4; ++r) {
        itm[r] = pack2(hsum2(a0[r]), hsum2(a1[r]));
      }

      // quad reduce-scatter over lane bits 0-1 (= kq): lane ends with row 4p+kq
      ull i01k = b0 ? itm[1] : itm[0];
      ull i01g = b0 ? itm[0] : itm[1];
      ull k2a = add2(i01k, __shfl_xor_sync(0xffffffffu, i01g, 1));
      ull i23k = b0 ? itm[3] : itm[2];
      ull i23g = b0 ? itm[2] : itm[3];
      ull k2b = add2(i23k, __shfl_xor_sync(0xffffffffu, i23g, 1));
      ull keep = b1 ? k2b : k2a;
      ull give = b1 ? k2a : k2b;
      ull tot = add2(keep, __shfl_xor_sync(0xffffffffu, give, 2));

      float r0, r1;
      unpack2(tot, r0, r1);
      float* op =
          g_xproj + (rowbase + (size_t)c * 8 + 4 * p + kq) * HH + j0;
      *reinterpret_cast<float2*>(op) = make_float2(r0, r1);
    }

    if (c < 31 && tid < 256) {
      int row = tid >> 5, gg = tid & 31;
      reinterpret_cast<float4*>(sX[(c + 1) & 1])[row * 32 + (gg ^ (gg >> 3))] =
          pf;
    }
    __syncthreads();
  }
}

// ---------------------------------------------------------------------------
// Kernel 2: recurrence — VERBATIM the measured-2.455ms version. 128 CTAs x
// 512 thr, one CTA per batch pair. Thread (JQ = tid>>3, KH = tid&7):
// j in [4JQ,4JQ+4), k in [32KH,32KH+32). W: 80 floats/thread in regs + 48
// via conflict-free spread LDS.128. h double-buffered; in-warp octet reduce
// via shfl_xor(1,2,4); one barrier per step.
// ---------------------------------------------------------------------------
__global__ void __launch_bounds__(512, 1) recurrence_kernel(
    const float* __restrict__ hx, const float* __restrict__ W_hh,
    const float* __restrict__ W_actor, const float* __restrict__ W_critic,
    float* __restrict__ out) {
  extern __shared__ float smem[];
  ulonglong2* sW = reinterpret_cast<ulonglong2*>(smem);   // 12*512 u2
  float* shb = smem + 12 * 512 * 4;                       // [2 parity][2 b][288]

  const int tid = threadIdx.x;
  const int JQ = tid >> 3;       // 0..63
  const int KH = tid & 7;        // 0..7
  const int jb = JQ * 4;
  const int kb = KH * 32;
  const int b0g = blockIdx.x * 2;

  const int jf = JQ * 4 + (KH & 3);
  const int bf = KH >> 2;

  // ---- stage W regs: q = 0..4 ----
  ull wr[4][10];
  #pragma unroll
  for (int j = 0; j < 4; ++j) {
    const float4* wp =
        reinterpret_cast<const float4*>(W_hh + (jb + j) * HH + kb);
    #pragma unroll
    for (int q = 0; q < 5; ++q) {
      float4 f = __ldg(wp + q);
      wr[j][2 * q]     = pack2(f.x, f.y);
      wr[j][2 * q + 1] = pack2(f.z, f.w);
    }
  }
  // ---- stage W smem: q = 5..7 ----
  #pragma unroll
  for (int q = 5; q < 8; ++q) {
    #pragma unroll
    for (int j = 0; j < 4; ++j) {
      float4 f = __ldg(reinterpret_cast<const float4*>(
          W_hh + (jb + j) * HH + kb) + q);
      ulonglong2 v;
      v.x = pack2(f.x, f.y);
      v.y = pack2(f.z, f.w);
      sW[((q - 5) * 4 + j) * 512 + tid] = v;
    }
  }

  // ---- init h ----
  float h_old = hx[(b0g + bf) * HH + jf];
  shb[bf * 288 + (jf >> 5) * 36 + (jf & 31)] = h_old;
  __syncthreads();

  const float* xqp = g_xproj + ((size_t)(b0g + bf) * TT) * HH + jf;
  float xq_cur = __ldg(xqp);

  for (int t = 0; t < TT; ++t) {
    const int rp = t & 1;
    float xq_nxt = 0.0f;
    if (t + 1 < TT) xq_nxt = __ldg(xqp + (size_t)(t + 1) * HH);

    const float* hbase = shb + rp * 576;
    const ulonglong2* hp0 =
        reinterpret_cast<const ulonglong2*>(hbase + KH * 36);
    const ulonglong2* hp1 =
        reinterpret_cast<const ulonglong2*>(hbase + 288 + KH * 36);

    ull a[8];
    #pragma unroll
    for (int i = 0; i < 8; ++i) a[i] = 0ull;

    #pragma unroll
    for (int q = 0; q < 8; ++q) {
      ulonglong2 v0 = hp0[q];
      ulonglong2 v1 = hp1[q];
      if (q < 5) {
        #pragma unroll
        for (int j = 0; j < 4; ++j) {
          a[j]     = ffma2(wr[j][2 * q],     v0.x, a[j]);
          a[j]     = ffma2(wr[j][2 * q + 1], v0.y, a[j]);
          a[4 + j] = ffma2(wr[j][2 * q],     v1.x, a[4 + j]);
          a[4 + j] = ffma2(wr[j][2 * q + 1], v1.y, a[4 + j]);
        }
      } else {
        #pragma unroll
        for (int j = 0; j < 4; ++j) {
          ulonglong2 wv = sW[((q - 5) * 4 + j) * 512 + tid];
          a[j]     = ffma2(wv.x, v0.x, a[j]);
          a[j]     = ffma2(wv.y, v0.y, a[j]);
          a[4 + j] = ffma2(wv.x, v1.x, a[4 + j]);
          a[4 + j] = ffma2(wv.y, v1.y, a[4 + j]);
        }
      }
    }

    // ---- octet reduce-scatter over KH bits ----
    const bool s0 = (tid & 1), s1 = (tid & 2), s2 = (tid & 4);
    ull w4[4];
    #pragma unroll
    for (int r = 0; r < 4; ++r) {
      ull keep = s0 ? a[2 * r + 1] : a[2 * r];
      ull give = s0 ? a[2 * r]     : a[2 * r + 1];
      ull recv = __shfl_xor_sync(0xffffffffu, give, 1);
      w4[r] = add2(keep, recv);
    }
    ull w2[2];
    #pragma unroll
    for (int r = 0; r < 2; ++r) {
      ull keep = s1 ? w4[2 * r + 1] : w4[2 * r];
      ull give = s1 ? w4[2 * r]     : w4[2 * r + 1];
      ull recv = __shfl_xor_sync(0xffffffffu, give, 2);
      w2[r] = add2(keep, recv);
    }
    ull keep = s2 ? w2[1] : w2[0];
    ull give = s2 ? w2[0] : w2[1];
    ull recv = __shfl_xor_sync(0xffffffffu, give, 4);
    ull tot = add2(keep, recv);

    // ---- finalize owned (b, j) ----
    float p = hsum2(tot) + xq_cur;
    h_old = 0.8f * h_old + 0.2f * fmaxf(p, 0.0f);
    shb[(rp ^ 1) * 576 + bf * 288 + (jf >> 5) * 36 + (jf & 31)] = h_old;
    xq_cur = xq_nxt;
    __syncthreads();
  }

  // -------- epilogue (final h in parity-0 buffer) --------
  const float* hf0 = shb;
  const float* hf1 = shb + 288;
  float* out_actor  = out;                 // [B][A]
  float* out_critic = out + BB * AA;       // [B]
  float* out_hx     = out + BB * AA + BB;  // [B][H]

  if (tid < HH) {
    int pj = (tid >> 5) * 36 + (tid & 31);
    out_hx[b0g * HH + tid]       = hf0[pj];
    out_hx[(b0g + 1) * HH + tid] = hf1[pj];
  }

  const int wid = tid >> 5, lane = tid & 31;
  if (wid < AA) {
    float pa0 = 0.f, pa1 = 0.f;
    for (int jj = lane; jj < HH; jj += 32) {
      int pj = (jj >> 5) * 36 + (jj & 31);
      float wa = W_actor[wid * HH + jj];
      pa0 += wa * hf0[pj];
      pa1 += wa * hf1[pj];
    }
    #pragma unroll
    for (int off = 16; off; off >>= 1) {
      pa0 += __shfl_down_sync(0xffffffffu, pa0, off);
      pa1 += __shfl_down_sync(0xffffffffu, pa1, off);
    }
    if (lane == 0) {
      out_actor[b0g * AA + wid]       = pa0;
      out_actor[(b0g + 1) * AA + wid] = pa1;
    }
  }
  if (wid == 8) {
    float pc0 = 0.f, pc1 = 0.f;
    for (int jj = lane; jj < HH; jj += 32) {
      int pj = (jj >> 5) * 36 + (jj & 31);
      float wc = W_critic[jj];
      pc0 += wc * hf0[pj];
      pc1 += wc * hf1[pj];
    }
    #pragma unroll
    for (int off = 16; off; off >>= 1) {
      pc0 += __shfl_down_sync(0xffffffffu, pc0, off);
      pc1 += __shfl_down_sync(0xffffffffu, pc1, off);
    }
    if (lane == 0) {
      out_critic[b0g]     = pc0;
      out_critic[b0g + 1] = pc1;
    }
  }
}

// ---------------------------------------------------------------------------
extern "C" void kernel_launch(void* const* d_in, const int* in_sizes, int n_in,
                              void* d_out, int out_size) {
  const float* x        = (const float*)d_in[0];
  const float* hx       = (const float*)d_in[1];
  const float* W_ih     = (const float*)d_in[2];
  const float* W_hh     = (const float*)d_in[3];
  const float* W_actor  = (const float*)d_in[4];
  const float* W_critic = (const float*)d_in[5];
  float* out = (float*)d_out;

  // recurrence smem: W 12*512*16B = 98304B + h 2*2*288*4B = 4608B
  const int smem2 = 98304 + 4608;
  cudaFuncSetAttribute(recurrence_kernel,
                       cudaFuncAttributeMaxDynamicSharedMemorySize, smem2);

  xproj_kernel<<<(BB * TT) / 256, 512>>>(x, W_ih);
  recurrence_kernel<<<BB / 2, 512, smem2>>>(hx, W_hh, W_actor, W_critic, out);
}

// round 15
// speedup vs baseline: 2.2010x; 1.2740x over previous
#include <cuda_runtime.h>
#include <cuda_bf16.h>
#include <cstdint>

#define BB 256
#define TT 2048
#define II 128
#define HH 256
#define AA 8

typedef unsigned long long ull;

// 512MB scratch for xproj[b][t][h]
__device__ float g_xproj[(size_t)BB * TT * HH];

__device__ __forceinline__ ull ffma2(ull a, ull b, ull c) {
  ull d;
  asm("fma.rn.f32x2 %0, %1, %2, %3;" : "=l"(d) : "l"(a), "l"(b), "l"(c));
  return d;
}
__device__ __forceinline__ ull add2(ull a, ull b) {
  ull d;
  asm("add.rn.f32x2 %0, %1, %2;" : "=l"(d) : "l"(a), "l"(b));
  return d;
}
__device__ __forceinline__ ull pack2(float lo, float hi) {
  ull d;
  asm("mov.b64 %0, {%1, %2};" : "=l"(d) : "f"(lo), "f"(hi));
  return d;
}
__device__ __forceinline__ float hsum2(ull v) {
  float lo, hi;
  asm("mov.b64 {%0, %1}, %2;" : "=f"(lo), "=f"(hi) : "l"(v));
  return lo + hi;
}
__device__ __forceinline__ uint32_t smem_u32(const void* p) {
  uint32_t a;
  asm("{ .reg .u64 t; cvta.to.shared.u64 t, %1; cvt.u32.u64 %0, t; }"
      : "=r"(a) : "l"(p));
  return a;
}
__device__ __forceinline__ uint32_t bf16pair(float a, float b) {
  __nv_bfloat162 t = __floats2bfloat162_rn(a, b);  // a -> low half
  return *reinterpret_cast<uint32_t*>(&t);
}
__device__ __forceinline__ void ldsm_x4(uint32_t addr, uint32_t& r0,
                                        uint32_t& r1, uint32_t& r2,
                                        uint32_t& r3) {
  asm volatile(
      "ldmatrix.sync.aligned.m8n8.x4.shared.b16 {%0,%1,%2,%3}, [%4];"
      : "=r"(r0), "=r"(r1), "=r"(r2), "=r"(r3) : "r"(addr));
}
__device__ __forceinline__ void mma16816(float* d, const uint32_t* a,
                                         uint32_t b0, uint32_t b1) {
  asm volatile(
      "mma.sync.aligned.m16n8k16.row.col.f32.bf16.bf16.f32 "
      "{%0,%1,%2,%3}, {%4,%5,%6,%7}, {%8,%9}, {%0,%1,%2,%3};"
      : "+f"(d[0]), "+f"(d[1]), "+f"(d[2]), "+f"(d[3])
      : "r"(a[0]), "r"(a[1]), "r"(a[2]), "r"(a[3]), "r"(b0), "r"(b1));
}

#define XSTR 136  // bf16 row stride: 272B -> ldmatrix rows hit all 32 banks

// ---------------------------------------------------------------------------
// Kernel 1: xproj via mma.sync bf16 (3-term hi/lo split: xh*Wh + xl*Wh +
// xh*Wl). 4096 CTAs x 512 thr; CTA = 128 rows x 256 j, K=128.
// smem: xh/xl [128][136] bf16, wh/wl [256][136] bf16 (208896 B).
// 16 warps as 4(M) x 4(N): warp owns 32 rows x 64 cols = 2 m16 x 8 n8 tiles.
// A/B frags via conflict-free ldmatrix.x4; acc fp32 in regs; direct STG.64.
// ---------------------------------------------------------------------------
__global__ void __launch_bounds__(512) xproj_kernel(
    const float* __restrict__ x, const float* __restrict__ W_ih) {
  extern __shared__ __align__(16) char smem[];
  __nv_bfloat16* sb = reinterpret_cast<__nv_bfloat16*>(smem);
  __nv_bfloat16* xh = sb;                 // [128][XSTR]
  __nv_bfloat16* xl = sb + 128 * XSTR;
  __nv_bfloat16* wh = sb + 2 * 128 * XSTR;  // [256][XSTR]
  __nv_bfloat16* wl = sb + 2 * 128 * XSTR + 256 * XSTR;

  const int tid = threadIdx.x;
  const int wid = tid >> 5, lane = tid & 31;
  const size_t rowbase = (size_t)blockIdx.x * 128;

  // ---- stage x tile: fp32 -> hi/lo bf16 ----
  const float2* xg2 = reinterpret_cast<const float2*>(x + rowbase * II);
  #pragma unroll
  for (int it = 0; it < 16; ++it) {
    int idx = it * 512 + tid;          // float2 index
    float2 v = __ldg(xg2 + idx);
    int row = idx >> 6, k2 = idx & 63; // k = 2*k2
    __nv_bfloat16 h0 = __float2bfloat16(v.x);
    __nv_bfloat16 h1 = __float2bfloat16(v.y);
    float r0 = v.x - __bfloat162float(h0);
    float r1 = v.y - __bfloat162float(h1);
    int e = row * XSTR + 2 * k2;
    *reinterpret_cast<uint32_t*>(xh + e) = bf16pair(v.x, v.y);
    *reinterpret_cast<uint32_t*>(xl + e) = bf16pair(r0, r1);
  }
  // ---- stage W: fp32 -> hi/lo bf16 ----
  const float2* wg2 = reinterpret_cast<const float2*>(W_ih);
  #pragma unroll
  for (int it = 0; it < 32; ++it) {
    int idx = it * 512 + tid;
    float2 v = __ldg(wg2 + idx);
    int j = idx >> 6, k2 = idx & 63;
    __nv_bfloat16 h0 = __float2bfloat16(v.x);
    __nv_bfloat16 h1 = __float2bfloat16(v.y);
    float r0 = v.x - __bfloat162float(h0);
    float r1 = v.y - __bfloat162float(h1);
    int e = j * XSTR + 2 * k2;
    *reinterpret_cast<uint32_t*>(wh + e) = bf16pair(v.x, v.y);
    *reinterpret_cast<uint32_t*>(wl + e) = bf16pair(r0, r1);
  }
  __syncthreads();

  // ---- MMA phase ----
  const int mbase = (wid & 3) * 32;    // 2 m16 tiles
  const int nbase = (wid >> 2) * 64;   // 8 n8 tiles

  // per-lane ldmatrix row addressing
  const int arow = lane & 15, ahalf = lane >> 4;          // A: x4 = one m16k16
  const int brow = lane & 7, bk = (lane >> 3) & 1, btile = lane >> 4;  // B

  const uint32_t xh_u = smem_u32(xh), xl_u = smem_u32(xl);
  const uint32_t wh_u = smem_u32(wh), wl_u = smem_u32(wl);
  // A lane byte offset (within term base), excluding k and mt terms:
  const uint32_t aoff = (uint32_t)(((mbase + arow) * XSTR + 8 * ahalf) * 2);
  // B lane byte offset excluding k/ntp/terms:
  const uint32_t boff =
      (uint32_t)(((nbase + btile * 8 + brow) * XSTR + 8 * bk) * 2);

  float acc[2][8][4];
  #pragma unroll
  for (int mt = 0; mt < 2; ++mt)
    #pragma unroll
    for (int nt = 0; nt < 8; ++nt)
      #pragma unroll
      for (int u = 0; u < 4; ++u) acc[mt][nt][u] = 0.0f;

  #pragma unroll
  for (int term = 0; term < 3; ++term) {
    const uint32_t abase = (term == 1 ? xl_u : xh_u) + aoff;
    const uint32_t bbase = (term == 2 ? wl_u : wh_u) + boff;
    for (int k8 = 0; k8 < 8; ++k8) {  // k chunk of 16
      const uint32_t koff = (uint32_t)(k8 * 32);  // 16 bf16 = 32B
      uint32_t a[2][4];
      #pragma unroll
      for (int mt = 0; mt < 2; ++mt) {
        ldsm_x4(abase + koff + (uint32_t)(mt * 16 * XSTR * 2),
                a[mt][0], a[mt][1], a[mt][2], a[mt][3]);
      }
      #pragma unroll
      for (int ntp = 0; ntp < 4; ++ntp) {  // pair of n8 tiles
        uint32_t b0, b1, b2, b3;
        ldsm_x4(bbase + koff + (uint32_t)(ntp * 16 * XSTR * 2), b0, b1, b2,
                b3);
        #pragma unroll
        for (int mt = 0; mt < 2; ++mt) {
          mma16816(acc[mt][2 * ntp],     a[mt], b0, b1);
          mma16816(acc[mt][2 * ntp + 1], a[mt], b2, b3);
        }
      }
    }
  }

  // ---- epilogue: direct STG.64 (32B-coalesced per lane quad) ----
  #pragma unroll
  for (int mt = 0; mt < 2; ++mt) {
    #pragma unroll
    for (int nt = 0; nt < 8; ++nt) {
      int r0 = mbase + mt * 16 + (lane >> 2);
      int c = nbase + nt * 8 + 2 * (lane & 3);
      float* p = g_xproj + (rowbase + r0) * HH + c;
      *reinterpret_cast<float2*>(p) =
          make_float2(acc[mt][nt][0], acc[mt][nt][1]);
      *reinterpret_cast<float2*>(p + 8 * HH) =
          make_float2(acc[mt][nt][2], acc[mt][nt][3]);
    }
  }
}

// ---------------------------------------------------------------------------
// Kernel 2: recurrence — VERBATIM the measured-2.46ms version.
// ---------------------------------------------------------------------------
__global__ void __launch_bounds__(512, 1) recurrence_kernel(
    const float* __restrict__ hx, const float* __restrict__ W_hh,
    const float* __restrict__ W_actor, const float* __restrict__ W_critic,
    float* __restrict__ out) {
  extern __shared__ float smemf[];
  ulonglong2* sW = reinterpret_cast<ulonglong2*>(smemf);  // 12*512 u2
  float* shb = smemf + 12 * 512 * 4;                      // [2 parity][2 b][288]

  const int tid = threadIdx.x;
  const int JQ = tid >> 3;
  const int KH = tid & 7;
  const int jb = JQ * 4;
  const int kb = KH * 32;
  const int b0g = blockIdx.x * 2;

  const int jf = JQ * 4 + (KH & 3);
  const int bf = KH >> 2;

  ull wr[4][10];
  #pragma unroll
  for (int j = 0; j < 4; ++j) {
    const float4* wp =
        reinterpret_cast<const float4*>(W_hh + (jb + j) * HH + kb);
    #pragma unroll
    for (int q = 0; q < 5; ++q) {
      float4 f = __ldg(wp + q);
      wr[j][2 * q]     = pack2(f.x, f.y);
      wr[j][2 * q + 1] = pack2(f.z, f.w);
    }
  }
  #pragma unroll
  for (int q = 5; q < 8; ++q) {
    #pragma unroll
    for (int j = 0; j < 4; ++j) {
      float4 f = __ldg(reinterpret_cast<const float4*>(
          W_hh + (jb + j) * HH + kb) + q);
      ulonglong2 v;
      v.x = pack2(f.x, f.y);
      v.y = pack2(f.z, f.w);
      sW[((q - 5) * 4 + j) * 512 + tid] = v;
    }
  }

  float h_old = hx[(b0g + bf) * HH + jf];
  shb[bf * 288 + (jf >> 5) * 36 + (jf & 31)] = h_old;
  __syncthreads();

  const float* xqp = g_xproj + ((size_t)(b0g + bf) * TT) * HH + jf;
  float xq_cur = __ldg(xqp);

  for (int t = 0; t < TT; ++t) {
    const int rp = t & 1;
    float xq_nxt = 0.0f;
    if (t + 1 < TT) xq_nxt = __ldg(xqp + (size_t)(t + 1) * HH);

    const float* hbase = shb + rp * 576;
    const ulonglong2* hp0 =
        reinterpret_cast<const ulonglong2*>(hbase + KH * 36);
    const ulonglong2* hp1 =
        reinterpret_cast<const ulonglong2*>(hbase + 288 + KH * 36);

    ull a[8];
    #pragma unroll
    for (int i = 0; i < 8; ++i) a[i] = 0ull;

    #pragma unroll
    for (int q = 0; q < 8; ++q) {
      ulonglong2 v0 = hp0[q];
      ulonglong2 v1 = hp1[q];
      if (q < 5) {
        #pragma unroll
        for (int j = 0; j < 4; ++j) {
          a[j]     = ffma2(wr[j][2 * q],     v0.x, a[j]);
          a[j]     = ffma2(wr[j][2 * q + 1], v0.y, a[j]);
          a[4 + j] = ffma2(wr[j][2 * q],     v1.x, a[4 + j]);
          a[4 + j] = ffma2(wr[j][2 * q + 1], v1.y, a[4 + j]);
        }
      } else {
        #pragma unroll
        for (int j = 0; j < 4; ++j) {
          ulonglong2 wv = sW[((q - 5) * 4 + j) * 512 + tid];
          a[j]     = ffma2(wv.x, v0.x, a[j]);
          a[j]     = ffma2(wv.y, v0.y, a[j]);
          a[4 + j] = ffma2(wv.x, v1.x, a[4 + j]);
          a[4 + j] = ffma2(wv.y, v1.y, a[4 + j]);
        }
      }
    }

    const bool s0 = (tid & 1), s1 = (tid & 2), s2 = (tid & 4);
    ull w4[4];
    #pragma unroll
    for (int r = 0; r < 4; ++r) {
      ull keep = s0 ? a[2 * r + 1] : a[2 * r];
      ull give = s0 ? a[2 * r]     : a[2 * r + 1];
      ull recv = __shfl_xor_sync(0xffffffffu, give, 1);
      w4[r] = add2(keep, recv);
    }
    ull w2[2];
    #pragma unroll
    for (int r = 0; r < 2; ++r) {
      ull keep = s1 ? w4[2 * r + 1] : w4[2 * r];
      ull give = s1 ? w4[2 * r]     : w4[2 * r + 1];
      ull recv = __shfl_xor_sync(0xffffffffu, give, 2);
      w2[r] = add2(keep, recv);
    }
    ull keep = s2 ? w2[1] : w2[0];
    ull give = s2 ? w2[0] : w2[1];
    ull recv = __shfl_xor_sync(0xffffffffu, give, 4);
    ull tot = add2(keep, recv);

    float p = hsum2(tot) + xq_cur;
    h_old = 0.8f * h_old + 0.2f * fmaxf(p, 0.0f);
    shb[(rp ^ 1) * 576 + bf * 288 + (jf >> 5) * 36 + (jf & 31)] = h_old;
    xq_cur = xq_nxt;
    __syncthreads();
  }

  const float* hf0 = shb;
  const float* hf1 = shb + 288;
  float* out_actor  = out;
  float* out_critic = out + BB * AA;
  float* out_hx     = out + BB * AA + BB;

  if (tid < HH) {
    int pj = (tid >> 5) * 36 + (tid & 31);
    out_hx[b0g * HH + tid]       = hf0[pj];
    out_hx[(b0g + 1) * HH + tid] = hf1[pj];
  }

  const int wid = tid >> 5, lane = tid & 31;
  if (wid < AA) {
    float pa0 = 0.f, pa1 = 0.f;
    for (int jj = lane; jj < HH; jj += 32) {
      int pj = (jj >> 5) * 36 + (jj & 31);
      float wa = W_actor[wid * HH + jj];
      pa0 += wa * hf0[pj];
      pa1 += wa * hf1[pj];
    }
    #pragma unroll
    for (int off = 16; off; off >>= 1) {
      pa0 += __shfl_down_sync(0xffffffffu, pa0, off);
      pa1 += __shfl_down_sync(0xffffffffu, pa1, off);
    }
    if (lane == 0) {
      out_actor[b0g * AA + wid]       = pa0;
      out_actor[(b0g + 1) * AA + wid] = pa1;
    }
  }
  if (wid == 8) {
    float pc0 = 0.f, pc1 = 0.f;
    for (int jj = lane; jj < HH; jj += 32) {
      int pj = (jj >> 5) * 36 + (jj & 31);
      float wc = W_critic[jj];
      pc0 += wc * hf0[pj];
      pc1 += wc * hf1[pj];
    }
    #pragma unroll
    for (int off = 16; off; off >>= 1) {
      pc0 += __shfl_down_sync(0xffffffffu, pc0, off);
      pc1 += __shfl_down_sync(0xffffffffu, pc1, off);
    }
    if (lane == 0) {
      out_critic[b0g]     = pc0;
      out_critic[b0g + 1] = pc1;
    }
  }
}

// ---------------------------------------------------------------------------
extern "C" void kernel_launch(void* const* d_in, const int* in_sizes, int n_in,
                              void* d_out, int out_size) {
  const float* x        = (const float*)d_in[0];
  const float* hx       = (const float*)d_in[1];
  const float* W_ih     = (const float*)d_in[2];
  const float* W_hh     = (const float*)d_in[3];
  const float* W_actor  = (const float*)d_in[4];
  const float* W_critic = (const float*)d_in[5];
  float* out = (float*)d_out;

  const int smem1 = (2 * 128 * XSTR + 2 * 256 * XSTR) * 2;  // 208896 B
  const int smem2 = 98304 + 4608;

  cudaFuncSetAttribute(xproj_kernel,
                       cudaFuncAttributeMaxDynamicSharedMemorySize, smem1);
  cudaFuncSetAttribute(recurrence_kernel,
                       cudaFuncAttributeMaxDynamicSharedMemorySize, smem2);

  xproj_kernel<<<(BB * TT) / 128, 512, smem1>>>(x, W_ih);
  recurrence_kernel<<<BB / 2, 512, smem2>>>(hx, W_hh, W_actor, W_critic, out);
}